// round 14
// baseline (speedup 1.0000x reference)
#include <cuda_runtime.h>
#include <cuda_fp16.h>
#include <cstdint>

// ---------------------------------------------------------------------------
// Network_1760936591970 (sm_103): fp16 2-split (Dekker) x 3-MMA emulated-fp32
// GEMM on mma.sync.m16n8k16.f16. 512-thread CTAs (16 warps, 64x32 warp tiles).
// R12: 3-stage cp.async pipeline (BKT=32, wait_group<=1), 80B padded rows
// (conflict-free, no XOR swizzle), merged weight prep.
// 256 -> 512 -> 512 -> 256 MLP, fused row softmax, B=65536, fp32 I/O.
// ---------------------------------------------------------------------------

#define BATCH 65536
#define MT 128
#define NT 256
#define BKT 32                 // K elems per stage = 16 half2 pairs = 64 B/row
#define ROWB 80                // 64 B data + 16 B pad -> conflict-free banks
#define A_H_OFF 0
#define A_L_OFF 10240          // 128 * 80
#define B_H_OFF 20480
#define B_L_OFF 40960          // B_H + 256*80
#define STAGE_BYTES 61440      // 40960 + 20480
#define NSTAGE 3
#define NTHREADS 512

// pre-split scratch (uint32 = packed half2 covering k,k+1)
__device__ uint32_t g_dH[BATCH * 128];     // data   [B][256/2]
__device__ uint32_t g_dL[BATCH * 128];
__device__ uint32_t g_h1H[BATCH * 256];    // h1     [B][512/2]
__device__ uint32_t g_h1L[BATCH * 256];
__device__ uint32_t g_h2H[BATCH * 256];    // h2     [B][512/2]
__device__ uint32_t g_h2L[BATCH * 256];
// weights transposed [N][K/2]: L1 @0, L2 @65536, L3 @196608
__device__ uint32_t g_wH[262144];
__device__ uint32_t g_wL[262144];

// ---------------- helpers ----------------
__device__ __forceinline__ void split_h(float x, uint16_t& h, uint16_t& l) {
    __half hh = __float2half_rn(x);
    __half ll = __float2half_rn(x - __half2float(hh));
    h = __half_as_ushort(hh);
    l = __half_as_ushort(ll);
}
__device__ __forceinline__ uint32_t pack2(uint16_t a, uint16_t b) {
    return (uint32_t)a | ((uint32_t)b << 16);
}
__device__ __forceinline__ uint32_t smem_u32(const void* p) {
    uint32_t a;
    asm("{ .reg .u64 t; cvta.to.shared.u64 t, %1; cvt.u32.u64 %0, t; }" : "=r"(a) : "l"(p));
    return a;
}
__device__ __forceinline__ void mma16(float* c, const uint32_t* a, uint32_t b0, uint32_t b1) {
    asm volatile(
        "mma.sync.aligned.m16n8k16.row.col.f32.f16.f16.f32 "
        "{%0,%1,%2,%3},{%4,%5,%6,%7},{%8,%9},{%0,%1,%2,%3};"
        : "+f"(c[0]), "+f"(c[1]), "+f"(c[2]), "+f"(c[3])
        : "r"(a[0]), "r"(a[1]), "r"(a[2]), "r"(a[3]), "r"(b0), "r"(b1));
}
__device__ __forceinline__ void cpa16(uint32_t dst, const void* src) {
    asm volatile("cp.async.cg.shared.global [%0], [%1], 16;" :: "r"(dst), "l"(src));
}
__device__ __forceinline__ float fast_tanh(float x) {
    float xc = fminf(fmaxf(x, -10.f), 10.f);
    float t = __expf(2.f * xc);
    return __fdividef(t - 1.f, t + 1.f);
}
__device__ __forceinline__ float act_f(float x, const float* a) {
    return a[1] * fast_tanh(x) * sinf(a[2] * x + a[3]) + a[4] * x + a[5];
}

// ---------------- prep kernels ----------------
// all three weight matrices in one launch; i indexes the packed [N][K/2] dest
__global__ void prep_w_all(const float* __restrict__ W1, const float* __restrict__ W2,
                           const float* __restrict__ W3,
                           uint32_t* __restrict__ th, uint32_t* __restrict__ tl)
{
    int i = blockIdx.x * 256 + threadIdx.x;        // 0 .. 262143
    const float* W; int K, N, base;
    if (i < 65536)       { W = W1; K = 256; N = 512; base = 0; }
    else if (i < 196608) { W = W2; K = 512; N = 512; base = 65536; }
    else                 { W = W3; K = 512; N = 256; base = 196608; }
    const int j = i - base, Kp = K >> 1;
    const int n = j / Kp, p = j - n * Kp;
    uint16_t h0, l0, h1, l1;
    split_h(W[(size_t)(2 * p) * N + n], h0, l0);
    split_h(W[(size_t)(2 * p + 1) * N + n], h1, l1);
    th[i] = pack2(h0, h1);
    tl[i] = pack2(l0, l1);
}
__global__ void prep_a(const float* __restrict__ A, uint32_t* __restrict__ th,
                       uint32_t* __restrict__ tl, int n4)
{
    int i = blockIdx.x * 256 + threadIdx.x;
    if (i >= n4) return;
    float4 v = *(const float4*)(A + (size_t)i * 4);
    uint16_t h0, l0, h1, l1, h2, l2, h3, l3;
    split_h(v.x, h0, l0); split_h(v.y, h1, l1);
    split_h(v.z, h2, l2); split_h(v.w, h3, l3);
    th[2 * i]     = pack2(h0, h1);  tl[2 * i]     = pack2(l0, l1);
    th[2 * i + 1] = pack2(h2, h3);  tl[2 * i + 1] = pack2(l2, l3);
}

// ---------------- fused GEMM ----------------
// 16 warps: wm = warp&1 (64-row halves), wn = warp>>1 (8 x 32-col blocks).
// MODE 0: out = split(act(A@Wt + b)) packed -> outH/outL [M][Nn/2]
// MODE 1: out = softmax(act(A@Wt + b)) -> outF (Nn==256, grid.x==1)
template <int MODE>
__global__ void __launch_bounds__(NTHREADS, 1)
gemm_tc(const uint32_t* __restrict__ AH, const uint32_t* __restrict__ AL,
        const uint32_t* __restrict__ BH, const uint32_t* __restrict__ BL,
        const float* __restrict__ bias, const float* __restrict__ actp,
        uint32_t* __restrict__ outH, uint32_t* __restrict__ outL,
        float* __restrict__ outF, int K, int Nn)
{
    extern __shared__ char smem[];
    __shared__ float psm[NT * 6];

    const int tid  = threadIdx.x;
    const int lane = tid & 31;
    const int warp = tid >> 5;
    const int wm   = warp & 1;    // 0..1 -> 64-row half
    const int wn   = warp >> 1;   // 0..7 -> 32-col block
    const int g    = lane >> 2;
    const int tg   = lane & 3;
    const int m0   = blockIdx.y * MT;
    const int n0   = blockIdx.x * NT;
    const int Kp   = K >> 1;
    const uint32_t sb = smem_u32(smem);

    for (int c = tid; c < NT; c += NTHREADS) {
        psm[c * 6 + 0] = bias[n0 + c];
        #pragma unroll
        for (int j = 0; j < 5; j++) psm[c * 6 + 1 + j] = actp[(n0 + c) * 5 + j];
    }

    float acc[4][4][4];
    #pragma unroll
    for (int i = 0; i < 4; i++)
        #pragma unroll
        for (int j = 0; j < 4; j++)
            #pragma unroll
            for (int c = 0; c < 4; c++) acc[i][j][c] = 0.f;

    const int kIters = K / BKT;           // 8 (K=256) or 16 (K=512)
    const int ar = tid >> 2, q = tid & 3; // row 0..127, 16B chunk 0..3

    auto issue = [&](int it) {
        const uint32_t stb = sb + (it % NSTAGE) * STAGE_BYTES;
        const int p0 = it * 16;                       // first k-pair of stage
        {   // A hi+lo: 128 rows x 4 chunks, 1 chunk per thread per array
            const uint32_t off = ar * ROWB + q * 16;
            const size_t src = (size_t)(m0 + ar) * Kp + p0 + q * 4;
            cpa16(stb + A_H_OFF + off, AH + src);
            cpa16(stb + A_L_OFF + off, AL + src);
        }
        #pragma unroll
        for (int i = 0; i < 2; i++) {                 // B hi+lo: 256 rows
            const int n = ar + i * 128;
            const uint32_t off = n * ROWB + q * 16;
            const size_t src = (size_t)(n0 + n) * Kp + p0 + q * 4;
            cpa16(stb + B_H_OFF + off, BH + src);
            cpa16(stb + B_L_OFF + off, BL + src);
        }
        asm volatile("cp.async.commit_group;" ::: "memory");
    };

    issue(0);
    issue(1);

    for (int it = 0; it < kIters; it++) {
        if (it + 1 < kIters)
            asm volatile("cp.async.wait_group 1;" ::: "memory");  // stage it done
        else
            asm volatile("cp.async.wait_group 0;" ::: "memory");  // final drain
        __syncthreads();
        // stage (it+2)%NSTAGE was last read in iteration it-1 (all warps past
        // that before this barrier) -> safe to refill now, overlapping compute.
        if (it + 2 < kIters) issue(it + 2);

        const char* st = smem + (it % NSTAGE) * STAGE_BYTES;
        #pragma unroll
        for (int kk = 0; kk < 2; kk++) {       // 2 k16-slices per stage
            const int pA = kk * 8 + tg;        // pairs pA, pA+4
            uint32_t ah[4][4], al[4][4];
            #pragma unroll
            for (int mi = 0; mi < 4; mi++) {
                const int m = wm * 64 + mi * 16 + g;
                const uint32_t o00 = m * ROWB + pA * 4;
                const uint32_t o10 = (m + 8) * ROWB + pA * 4;
                ah[mi][0] = *(const uint32_t*)(st + A_H_OFF + o00);
                ah[mi][1] = *(const uint32_t*)(st + A_H_OFF + o10);
                ah[mi][2] = *(const uint32_t*)(st + A_H_OFF + o00 + 16);
                ah[mi][3] = *(const uint32_t*)(st + A_H_OFF + o10 + 16);
                al[mi][0] = *(const uint32_t*)(st + A_L_OFF + o00);
                al[mi][1] = *(const uint32_t*)(st + A_L_OFF + o10);
                al[mi][2] = *(const uint32_t*)(st + A_L_OFF + o00 + 16);
                al[mi][3] = *(const uint32_t*)(st + A_L_OFF + o10 + 16);
            }
            // ni-pairs: dep distance 8 between writes to the same accumulator
            #pragma unroll
            for (int np = 0; np < 2; np++) {
                uint32_t bh[2][2], bl[2][2];
                #pragma unroll
                for (int p = 0; p < 2; p++) {
                    const int n = wn * 32 + (np * 2 + p) * 8 + g;
                    const uint32_t o0 = n * ROWB + pA * 4;
                    bh[p][0] = *(const uint32_t*)(st + B_H_OFF + o0);
                    bh[p][1] = *(const uint32_t*)(st + B_H_OFF + o0 + 16);
                    bl[p][0] = *(const uint32_t*)(st + B_L_OFF + o0);
                    bl[p][1] = *(const uint32_t*)(st + B_L_OFF + o0 + 16);
                }
                #pragma unroll
                for (int p = 0; p < 2; p++)
                    #pragma unroll
                    for (int mi = 0; mi < 4; mi++)
                        mma16(acc[mi][np * 2 + p], ah[mi], bh[p][0], bh[p][1]);
                #pragma unroll
                for (int p = 0; p < 2; p++)
                    #pragma unroll
                    for (int mi = 0; mi < 4; mi++)
                        mma16(acc[mi][np * 2 + p], al[mi], bh[p][0], bh[p][1]);
                #pragma unroll
                for (int p = 0; p < 2; p++)
                    #pragma unroll
                    for (int mi = 0; mi < 4; mi++)
                        mma16(acc[mi][np * 2 + p], ah[mi], bl[p][0], bl[p][1]);
            }
        }
    }

    // ---- epilogue: bias + activation ----
    #pragma unroll
    for (int mi = 0; mi < 4; mi++)
        #pragma unroll
        for (int ni = 0; ni < 4; ni++) {
            const int cw = wn * 32 + ni * 8 + 2 * tg;
            const float* p0 = &psm[cw * 6];
            const float* p1 = &psm[(cw + 1) * 6];
            acc[mi][ni][0] = act_f(acc[mi][ni][0] + p0[0], p0);
            acc[mi][ni][1] = act_f(acc[mi][ni][1] + p1[0], p1);
            acc[mi][ni][2] = act_f(acc[mi][ni][2] + p0[0], p0);
            acc[mi][ni][3] = act_f(acc[mi][ni][3] + p1[0], p1);
        }

    if (MODE == 0) {
        const int Np = Nn >> 1;
        #pragma unroll
        for (int mi = 0; mi < 4; mi++)
            #pragma unroll
            for (int ni = 0; ni < 4; ni++) {
                const int cw = wn * 32 + ni * 8 + 2 * tg;
                const int cp = (n0 + cw) >> 1;
                const int r0 = m0 + wm * 64 + mi * 16 + g;
                uint16_t h0, l0, h1, l1;
                split_h(acc[mi][ni][0], h0, l0);
                split_h(acc[mi][ni][1], h1, l1);
                outH[(size_t)r0 * Np + cp] = pack2(h0, h1);
                outL[(size_t)r0 * Np + cp] = pack2(l0, l1);
                split_h(acc[mi][ni][2], h0, l0);
                split_h(acc[mi][ni][3], h1, l1);
                outH[(size_t)(r0 + 8) * Np + cp] = pack2(h0, h1);
                outL[(size_t)(r0 + 8) * Np + cp] = pack2(l0, l1);
            }
    } else {
        // fused softmax over full row (Nn == 256 in this CTA); 8 wn partials
        float* red = (float*)smem;   // [128 rows][8]
        float pmax[4][2], rmax[4][2], psum[4][2], rsum[4][2];

        #pragma unroll
        for (int mi = 0; mi < 4; mi++)
            #pragma unroll
            for (int h = 0; h < 2; h++) {
                float v = -3.4e38f;
                #pragma unroll
                for (int ni = 0; ni < 4; ni++)
                    v = fmaxf(v, fmaxf(acc[mi][ni][2 * h], acc[mi][ni][2 * h + 1]));
                v = fmaxf(v, __shfl_xor_sync(0xFFFFFFFFu, v, 1));
                v = fmaxf(v, __shfl_xor_sync(0xFFFFFFFFu, v, 2));
                pmax[mi][h] = v;
            }
        __syncthreads();   // mainloop smem reads done before reuse as 'red'
        if (tg == 0)
            #pragma unroll
            for (int mi = 0; mi < 4; mi++)
                #pragma unroll
                for (int h = 0; h < 2; h++)
                    red[(wm * 64 + mi * 16 + g + 8 * h) * 8 + wn] = pmax[mi][h];
        __syncthreads();
        #pragma unroll
        for (int mi = 0; mi < 4; mi++)
            #pragma unroll
            for (int h = 0; h < 2; h++) {
                const int wr = wm * 64 + mi * 16 + g + 8 * h;
                float v = red[wr * 8 + 0];
                #pragma unroll
                for (int j = 1; j < 8; j++) v = fmaxf(v, red[wr * 8 + j]);
                rmax[mi][h] = v;
            }
        __syncthreads();

        #pragma unroll
        for (int mi = 0; mi < 4; mi++)
            #pragma unroll
            for (int h = 0; h < 2; h++) {
                float s = 0.f;
                #pragma unroll
                for (int ni = 0; ni < 4; ni++) {
                    float e0 = __expf(acc[mi][ni][2 * h]     - rmax[mi][h]);
                    float e1 = __expf(acc[mi][ni][2 * h + 1] - rmax[mi][h]);
                    acc[mi][ni][2 * h]     = e0;
                    acc[mi][ni][2 * h + 1] = e1;
                    s += e0 + e1;
                }
                s += __shfl_xor_sync(0xFFFFFFFFu, s, 1);
                s += __shfl_xor_sync(0xFFFFFFFFu, s, 2);
                psum[mi][h] = s;
            }
        if (tg == 0)
            #pragma unroll
            for (int mi = 0; mi < 4; mi++)
                #pragma unroll
                for (int h = 0; h < 2; h++)
                    red[(wm * 64 + mi * 16 + g + 8 * h) * 8 + wn] = psum[mi][h];
        __syncthreads();
        #pragma unroll
        for (int mi = 0; mi < 4; mi++)
            #pragma unroll
            for (int h = 0; h < 2; h++) {
                const int wr = wm * 64 + mi * 16 + g + 8 * h;
                float s = red[wr * 8 + 0];
                #pragma unroll
                for (int j = 1; j < 8; j++) s += red[wr * 8 + j];
                rsum[mi][h] = 1.0f / s;
            }

        #pragma unroll
        for (int mi = 0; mi < 4; mi++)
            #pragma unroll
            for (int ni = 0; ni < 4; ni++) {
                const int col = wn * 32 + ni * 8 + 2 * tg;
                const int r0 = m0 + wm * 64 + mi * 16 + g;
                *(float2*)(outF + (size_t)r0 * 256 + col) =
                    make_float2(acc[mi][ni][0] * rsum[mi][0],
                                acc[mi][ni][1] * rsum[mi][0]);
                *(float2*)(outF + (size_t)(r0 + 8) * 256 + col) =
                    make_float2(acc[mi][ni][2] * rsum[mi][1],
                                acc[mi][ni][3] * rsum[mi][1]);
            }
    }
}

// ---------------- launch ----------------
extern "C" void kernel_launch(void* const* d_in, const int* in_sizes, int n_in,
                              void* d_out, int out_size)
{
    (void)in_sizes; (void)n_in; (void)out_size;
    const float* data = (const float*)d_in[0];
    const float* W1   = (const float*)d_in[1];
    const float* b1   = (const float*)d_in[2];
    const float* a1   = (const float*)d_in[3];
    const float* W2   = (const float*)d_in[4];
    const float* b2   = (const float*)d_in[5];
    const float* a2   = (const float*)d_in[6];
    const float* W3   = (const float*)d_in[7];
    const float* b3   = (const float*)d_in[8];
    const float* a3   = (const float*)d_in[9];
    float* out = (float*)d_out;

    void* p;
    cudaGetSymbolAddress(&p, g_dH);  uint32_t* dH  = (uint32_t*)p;
    cudaGetSymbolAddress(&p, g_dL);  uint32_t* dL  = (uint32_t*)p;
    cudaGetSymbolAddress(&p, g_h1H); uint32_t* h1H = (uint32_t*)p;
    cudaGetSymbolAddress(&p, g_h1L); uint32_t* h1L = (uint32_t*)p;
    cudaGetSymbolAddress(&p, g_h2H); uint32_t* h2H = (uint32_t*)p;
    cudaGetSymbolAddress(&p, g_h2L); uint32_t* h2L = (uint32_t*)p;
    cudaGetSymbolAddress(&p, g_wH);  uint32_t* wH  = (uint32_t*)p;
    cudaGetSymbolAddress(&p, g_wL);  uint32_t* wL  = (uint32_t*)p;

    cudaFuncSetAttribute(gemm_tc<0>, cudaFuncAttributeMaxDynamicSharedMemorySize,
                         NSTAGE * STAGE_BYTES);
    cudaFuncSetAttribute(gemm_tc<1>, cudaFuncAttributeMaxDynamicSharedMemorySize,
                         NSTAGE * STAGE_BYTES);

    prep_w_all<<<1024, 256>>>(W1, W2, W3, wH, wL);
    prep_a<<<(BATCH * 64 + 255) / 256, 256>>>(data, dH, dL, BATCH * 64);

    dim3 blk(NTHREADS);
    gemm_tc<0><<<dim3(2, BATCH / MT), blk, NSTAGE * STAGE_BYTES>>>(
        dH, dL, wH, wL, b1, a1, h1H, h1L, nullptr, 256, 512);
    gemm_tc<0><<<dim3(2, BATCH / MT), blk, NSTAGE * STAGE_BYTES>>>(
        h1H, h1L, wH + 65536, wL + 65536, b2, a2, h2H, h2L, nullptr, 512, 512);
    gemm_tc<1><<<dim3(1, BATCH / MT), blk, NSTAGE * STAGE_BYTES>>>(
        h2H, h2L, wH + 196608, wL + 196608, b3, a3, nullptr, nullptr, out, 512, 256);
}

// round 15
// speedup vs baseline: 1.3130x; 1.3130x over previous
#include <cuda_runtime.h>
#include <cuda_fp16.h>
#include <cstdint>

// ---------------------------------------------------------------------------
// Network_1760936591970 (sm_103): fp16 2-split (Dekker) x 3-MMA emulated-fp32
// GEMM on mma.sync.m16n8k16.f16.
// R15: layers 1-2 use 256-thread CTAs (64x128 tile, 96KB smem, 2 CTAs/SM) so
// barriers/epilogue of one CTA overlap MMAs of the other. Layer 3 keeps the
// 512-thread 128x256 kernel with fused row softmax. 128B XOR-swizzled rows
// (store/load conflict-free), BKT=64, 2-stage single-barrier pipeline (r11).
// 256 -> 512 -> 512 -> 256 MLP, B=65536, fp32 I/O.
// ---------------------------------------------------------------------------

#define BATCH 65536
#define NTHREADS_S 256
#define NTHREADS_L 512

// small kernel (layers 1-2): 64x128 tile
#define S_MT 64
#define S_NT 128
#define S_AH 0
#define S_AL 8192
#define S_BH 16384
#define S_BL 32768
#define S_STAGE 49152          // 48KB; x2 stages = 96KB

// large kernel (layer 3): 128x256 tile
#define L_MT 128
#define L_NT 256
#define L_AH 0
#define L_AL 16384
#define L_BH 32768
#define L_BL 65536
#define L_STAGE 98304          // 96KB; x2 stages = 192KB

// pre-split scratch (uint32 = packed half2 covering k,k+1)
__device__ uint32_t g_dH[BATCH * 128];     // data   [B][256/2]
__device__ uint32_t g_dL[BATCH * 128];
__device__ uint32_t g_h1H[BATCH * 256];    // h1     [B][512/2]
__device__ uint32_t g_h1L[BATCH * 256];
__device__ uint32_t g_h2H[BATCH * 256];    // h2     [B][512/2]
__device__ uint32_t g_h2L[BATCH * 256];
// weights transposed [N][K/2]: L1 @0, L2 @65536, L3 @196608
__device__ uint32_t g_wH[262144];
__device__ uint32_t g_wL[262144];

// ---------------- helpers ----------------
__device__ __forceinline__ void split_h(float x, uint16_t& h, uint16_t& l) {
    __half hh = __float2half_rn(x);
    __half ll = __float2half_rn(x - __half2float(hh));
    h = __half_as_ushort(hh);
    l = __half_as_ushort(ll);
}
__device__ __forceinline__ uint32_t pack2(uint16_t a, uint16_t b) {
    return (uint32_t)a | ((uint32_t)b << 16);
}
__device__ __forceinline__ uint32_t smem_u32(const void* p) {
    uint32_t a;
    asm("{ .reg .u64 t; cvta.to.shared.u64 t, %1; cvt.u32.u64 %0, t; }" : "=r"(a) : "l"(p));
    return a;
}
__device__ __forceinline__ void mma16(float* c, const uint32_t* a, uint32_t b0, uint32_t b1) {
    asm volatile(
        "mma.sync.aligned.m16n8k16.row.col.f32.f16.f16.f32 "
        "{%0,%1,%2,%3},{%4,%5,%6,%7},{%8,%9},{%0,%1,%2,%3};"
        : "+f"(c[0]), "+f"(c[1]), "+f"(c[2]), "+f"(c[3])
        : "r"(a[0]), "r"(a[1]), "r"(a[2]), "r"(a[3]), "r"(b0), "r"(b1));
}
__device__ __forceinline__ void cpa16(uint32_t dst, const void* src) {
    asm volatile("cp.async.cg.shared.global [%0], [%1], 16;" :: "r"(dst), "l"(src));
}
__device__ __forceinline__ float fast_tanh(float x) {
    float xc = fminf(fmaxf(x, -10.f), 10.f);
    float t = __expf(2.f * xc);
    return __fdividef(t - 1.f, t + 1.f);
}
__device__ __forceinline__ float act_f(float x, const float* a) {
    return a[1] * fast_tanh(x) * sinf(a[2] * x + a[3]) + a[4] * x + a[5];
}
#define ROWOFF(row, kbyte) ((row) * 128 + ((kbyte) ^ (((row) & 7) << 4)))

// ---------------- prep kernels ----------------
__global__ void prep_w_all(const float* __restrict__ W1, const float* __restrict__ W2,
                           const float* __restrict__ W3,
                           uint32_t* __restrict__ th, uint32_t* __restrict__ tl)
{
    int i = blockIdx.x * 256 + threadIdx.x;        // 0 .. 262143
    const float* W; int K, N, base;
    if (i < 65536)       { W = W1; K = 256; N = 512; base = 0; }
    else if (i < 196608) { W = W2; K = 512; N = 512; base = 65536; }
    else                 { W = W3; K = 512; N = 256; base = 196608; }
    const int j = i - base, Kp = K >> 1;
    const int n = j / Kp, p = j - n * Kp;
    uint16_t h0, l0, h1, l1;
    split_h(W[(size_t)(2 * p) * N + n], h0, l0);
    split_h(W[(size_t)(2 * p + 1) * N + n], h1, l1);
    th[i] = pack2(h0, h1);
    tl[i] = pack2(l0, l1);
}
__global__ void prep_a(const float* __restrict__ A, uint32_t* __restrict__ th,
                       uint32_t* __restrict__ tl, int n4)
{
    int i = blockIdx.x * 256 + threadIdx.x;
    if (i >= n4) return;
    float4 v = *(const float4*)(A + (size_t)i * 4);
    uint16_t h0, l0, h1, l1, h2, l2, h3, l3;
    split_h(v.x, h0, l0); split_h(v.y, h1, l1);
    split_h(v.z, h2, l2); split_h(v.w, h3, l3);
    th[2 * i]     = pack2(h0, h1);  tl[2 * i]     = pack2(l0, l1);
    th[2 * i + 1] = pack2(h2, h3);  tl[2 * i + 1] = pack2(l2, l3);
}

// ---------------- small GEMM: 64x128 tile, 2 CTAs/SM, layers 1-2 ----------------
// 8 warps: wm = warp&1 (32-row halves), wn = warp>>1 (4 x 32-col blocks).
// out = split(act(A@Wt + b)) packed -> outH/outL [M][Nn/2]
__global__ void __launch_bounds__(NTHREADS_S, 2)
gemm_s(const uint32_t* __restrict__ AH, const uint32_t* __restrict__ AL,
       const uint32_t* __restrict__ BH, const uint32_t* __restrict__ BL,
       const float* __restrict__ bias, const float* __restrict__ actp,
       uint32_t* __restrict__ outH, uint32_t* __restrict__ outL, int K, int Nn)
{
    extern __shared__ char smem[];
    __shared__ float psm[S_NT * 6];

    const int tid  = threadIdx.x;
    const int lane = tid & 31;
    const int warp = tid >> 5;
    const int wm   = warp & 1;    // 0..1 -> 32-row half
    const int wn   = warp >> 1;   // 0..3 -> 32-col block
    const int g    = lane >> 2;
    const int tg   = lane & 3;
    const int m0   = blockIdx.y * S_MT;
    const int n0   = blockIdx.x * S_NT;
    const int Kp   = K >> 1;
    const uint32_t sb = smem_u32(smem);

    for (int c = tid; c < S_NT; c += NTHREADS_S) {
        psm[c * 6 + 0] = bias[n0 + c];
        #pragma unroll
        for (int j = 0; j < 5; j++) psm[c * 6 + 1 + j] = actp[(n0 + c) * 5 + j];
    }

    float acc[2][4][4];
    #pragma unroll
    for (int i = 0; i < 2; i++)
        #pragma unroll
        for (int j = 0; j < 4; j++)
            #pragma unroll
            for (int c = 0; c < 4; c++) acc[i][j][c] = 0.f;

    const int kIters = K / 64;            // BKT=64: 4 (K=256) or 8 (K=512)
    const int cr = tid >> 3, cq = tid & 7;

    auto issue = [&](int it) {
        const uint32_t stb = sb + (it & 1) * S_STAGE;
        const int p0 = it * 32;
        #pragma unroll
        for (int i = 0; i < 2; i++) {      // A hi+lo: 64 rows x 8 chunks
            const int m = cr + i * 32;
            const uint32_t off = ROWOFF(m, cq * 16);
            const size_t src = (size_t)(m0 + m) * Kp + p0 + cq * 4;
            cpa16(stb + S_AH + off, AH + src);
            cpa16(stb + S_AL + off, AL + src);
        }
        #pragma unroll
        for (int i = 0; i < 4; i++) {      // B hi+lo: 128 rows x 8 chunks
            const int n = cr + i * 32;
            const uint32_t off = ROWOFF(n, cq * 16);
            const size_t src = (size_t)(n0 + n) * Kp + p0 + cq * 4;
            cpa16(stb + S_BH + off, BH + src);
            cpa16(stb + S_BL + off, BL + src);
        }
        asm volatile("cp.async.commit_group;" ::: "memory");
    };

    issue(0);

    for (int it = 0; it < kIters; it++) {
        asm volatile("cp.async.wait_group 0;" ::: "memory");
        __syncthreads();
        if (it + 1 < kIters) issue(it + 1);

        const char* st = smem + (it & 1) * S_STAGE;
        #pragma unroll
        for (int kk = 0; kk < 4; kk++) {   // 4 k16-slices per stage
            const int pA = kk * 8 + tg;
            uint32_t ah[2][4], al[2][4];
            #pragma unroll
            for (int mi = 0; mi < 2; mi++) {
                const int m = wm * 32 + mi * 16 + g;
                const uint32_t o00 = ROWOFF(m,     pA * 4);
                const uint32_t o10 = ROWOFF(m + 8, pA * 4);
                const uint32_t o01 = ROWOFF(m,     (pA + 4) * 4);
                const uint32_t o11 = ROWOFF(m + 8, (pA + 4) * 4);
                ah[mi][0] = *(const uint32_t*)(st + S_AH + o00);
                ah[mi][1] = *(const uint32_t*)(st + S_AH + o10);
                ah[mi][2] = *(const uint32_t*)(st + S_AH + o01);
                ah[mi][3] = *(const uint32_t*)(st + S_AH + o11);
                al[mi][0] = *(const uint32_t*)(st + S_AL + o00);
                al[mi][1] = *(const uint32_t*)(st + S_AL + o10);
                al[mi][2] = *(const uint32_t*)(st + S_AL + o01);
                al[mi][3] = *(const uint32_t*)(st + S_AL + o11);
            }
            #pragma unroll
            for (int np = 0; np < 2; np++) {
                uint32_t bh[2][2], bl[2][2];
                #pragma unroll
                for (int p = 0; p < 2; p++) {
                    const int n = wn * 32 + (np * 2 + p) * 8 + g;
                    const uint32_t o0 = ROWOFF(n, pA * 4);
                    const uint32_t o1 = ROWOFF(n, (pA + 4) * 4);
                    bh[p][0] = *(const uint32_t*)(st + S_BH + o0);
                    bh[p][1] = *(const uint32_t*)(st + S_BH + o1);
                    bl[p][0] = *(const uint32_t*)(st + S_BL + o0);
                    bl[p][1] = *(const uint32_t*)(st + S_BL + o1);
                }
                #pragma unroll
                for (int p = 0; p < 2; p++)
                    #pragma unroll
                    for (int mi = 0; mi < 2; mi++)
                        mma16(acc[mi][np * 2 + p], ah[mi], bh[p][0], bh[p][1]);
                #pragma unroll
                for (int p = 0; p < 2; p++)
                    #pragma unroll
                    for (int mi = 0; mi < 2; mi++)
                        mma16(acc[mi][np * 2 + p], al[mi], bh[p][0], bh[p][1]);
                #pragma unroll
                for (int p = 0; p < 2; p++)
                    #pragma unroll
                    for (int mi = 0; mi < 2; mi++)
                        mma16(acc[mi][np * 2 + p], ah[mi], bl[p][0], bl[p][1]);
            }
        }
    }

    // epilogue: bias + activation + split-store
    const int Np = Nn >> 1;
    #pragma unroll
    for (int mi = 0; mi < 2; mi++)
        #pragma unroll
        for (int ni = 0; ni < 4; ni++) {
            const int cw = wn * 32 + ni * 8 + 2 * tg;
            const float* p0 = &psm[cw * 6];
            const float* p1 = &psm[(cw + 1) * 6];
            const int cp = (n0 + cw) >> 1;
            const int r0 = m0 + wm * 32 + mi * 16 + g;
            float v0 = act_f(acc[mi][ni][0] + p0[0], p0);
            float v1 = act_f(acc[mi][ni][1] + p1[0], p1);
            float v2 = act_f(acc[mi][ni][2] + p0[0], p0);
            float v3 = act_f(acc[mi][ni][3] + p1[0], p1);
            uint16_t h0, l0, h1, l1;
            split_h(v0, h0, l0); split_h(v1, h1, l1);
            outH[(size_t)r0 * Np + cp] = pack2(h0, h1);
            outL[(size_t)r0 * Np + cp] = pack2(l0, l1);
            split_h(v2, h0, l0); split_h(v3, h1, l1);
            outH[(size_t)(r0 + 8) * Np + cp] = pack2(h0, h1);
            outL[(size_t)(r0 + 8) * Np + cp] = pack2(l0, l1);
        }
}

// ---------------- large GEMM: 128x256 tile, layer 3 + fused softmax ----------------
// 16 warps: wm = warp&1 (64-row halves), wn = warp>>1 (8 x 32-col blocks).
__global__ void __launch_bounds__(NTHREADS_L, 1)
gemm_l3(const uint32_t* __restrict__ AH, const uint32_t* __restrict__ AL,
        const uint32_t* __restrict__ BH, const uint32_t* __restrict__ BL,
        const float* __restrict__ bias, const float* __restrict__ actp,
        float* __restrict__ outF, int K)
{
    extern __shared__ char smem[];
    __shared__ float psm[L_NT * 6];

    const int tid  = threadIdx.x;
    const int lane = tid & 31;
    const int warp = tid >> 5;
    const int wm   = warp & 1;
    const int wn   = warp >> 1;
    const int g    = lane >> 2;
    const int tg   = lane & 3;
    const int m0   = blockIdx.y * L_MT;
    const int Kp   = K >> 1;
    const uint32_t sb = smem_u32(smem);

    for (int c = tid; c < L_NT; c += NTHREADS_L) {
        psm[c * 6 + 0] = bias[c];
        #pragma unroll
        for (int j = 0; j < 5; j++) psm[c * 6 + 1 + j] = actp[c * 5 + j];
    }

    float acc[4][4][4];
    #pragma unroll
    for (int i = 0; i < 4; i++)
        #pragma unroll
        for (int j = 0; j < 4; j++)
            #pragma unroll
            for (int c = 0; c < 4; c++) acc[i][j][c] = 0.f;

    const int kIters = K / 64;
    const int cr = tid >> 3, cq = tid & 7;

    auto issue = [&](int it) {
        const uint32_t stb = sb + (it & 1) * L_STAGE;
        const int p0 = it * 32;
        #pragma unroll
        for (int i = 0; i < 2; i++) {          // A hi+lo: 128 rows
            const int m = cr + i * 64;
            const uint32_t off = ROWOFF(m, cq * 16);
            const size_t src = (size_t)(m0 + m) * Kp + p0 + cq * 4;
            cpa16(stb + L_AH + off, AH + src);
            cpa16(stb + L_AL + off, AL + src);
        }
        #pragma unroll
        for (int i = 0; i < 4; i++) {          // B hi+lo: 256 rows
            const int n = cr + i * 64;
            const uint32_t off = ROWOFF(n, cq * 16);
            const size_t src = (size_t)n * Kp + p0 + cq * 4;
            cpa16(stb + L_BH + off, BH + src);
            cpa16(stb + L_BL + off, BL + src);
        }
        asm volatile("cp.async.commit_group;" ::: "memory");
    };

    issue(0);

    for (int it = 0; it < kIters; it++) {
        asm volatile("cp.async.wait_group 0;" ::: "memory");
        __syncthreads();
        if (it + 1 < kIters) issue(it + 1);

        const char* st = smem + (it & 1) * L_STAGE;
        #pragma unroll
        for (int kk = 0; kk < 4; kk++) {
            const int pA = kk * 8 + tg;
            uint32_t ah[4][4], al[4][4];
            #pragma unroll
            for (int mi = 0; mi < 4; mi++) {
                const int m = wm * 64 + mi * 16 + g;
                const uint32_t o00 = ROWOFF(m,     pA * 4);
                const uint32_t o10 = ROWOFF(m + 8, pA * 4);
                const uint32_t o01 = ROWOFF(m,     (pA + 4) * 4);
                const uint32_t o11 = ROWOFF(m + 8, (pA + 4) * 4);
                ah[mi][0] = *(const uint32_t*)(st + L_AH + o00);
                ah[mi][1] = *(const uint32_t*)(st + L_AH + o10);
                ah[mi][2] = *(const uint32_t*)(st + L_AH + o01);
                ah[mi][3] = *(const uint32_t*)(st + L_AH + o11);
                al[mi][0] = *(const uint32_t*)(st + L_AL + o00);
                al[mi][1] = *(const uint32_t*)(st + L_AL + o10);
                al[mi][2] = *(const uint32_t*)(st + L_AL + o01);
                al[mi][3] = *(const uint32_t*)(st + L_AL + o11);
            }
            #pragma unroll
            for (int np = 0; np < 2; np++) {
                uint32_t bh[2][2], bl[2][2];
                #pragma unroll
                for (int p = 0; p < 2; p++) {
                    const int n = wn * 32 + (np * 2 + p) * 8 + g;
                    const uint32_t o0 = ROWOFF(n, pA * 4);
                    const uint32_t o1 = ROWOFF(n, (pA + 4) * 4);
                    bh[p][0] = *(const uint32_t*)(st + L_BH + o0);
                    bh[p][1] = *(const uint32_t*)(st + L_BH + o1);
                    bl[p][0] = *(const uint32_t*)(st + L_BL + o0);
                    bl[p][1] = *(const uint32_t*)(st + L_BL + o1);
                }
                #pragma unroll
                for (int p = 0; p < 2; p++)
                    #pragma unroll
                    for (int mi = 0; mi < 4; mi++)
                        mma16(acc[mi][np * 2 + p], ah[mi], bh[p][0], bh[p][1]);
                #pragma unroll
                for (int p = 0; p < 2; p++)
                    #pragma unroll
                    for (int mi = 0; mi < 4; mi++)
                        mma16(acc[mi][np * 2 + p], al[mi], bh[p][0], bh[p][1]);
                #pragma unroll
                for (int p = 0; p < 2; p++)
                    #pragma unroll
                    for (int mi = 0; mi < 4; mi++)
                        mma16(acc[mi][np * 2 + p], ah[mi], bl[p][0], bl[p][1]);
            }
        }
    }

    // epilogue: bias + activation
    #pragma unroll
    for (int mi = 0; mi < 4; mi++)
        #pragma unroll
        for (int ni = 0; ni < 4; ni++) {
            const int cw = wn * 32 + ni * 8 + 2 * tg;
            const float* p0 = &psm[cw * 6];
            const float* p1 = &psm[(cw + 1) * 6];
            acc[mi][ni][0] = act_f(acc[mi][ni][0] + p0[0], p0);
            acc[mi][ni][1] = act_f(acc[mi][ni][1] + p1[0], p1);
            acc[mi][ni][2] = act_f(acc[mi][ni][2] + p0[0], p0);
            acc[mi][ni][3] = act_f(acc[mi][ni][3] + p1[0], p1);
        }

    // fused softmax over full row (256 cols in this CTA); 8 wn partials
    float* red = (float*)smem;   // [128 rows][8]
    float pmax[4][2], rmax[4][2], psum[4][2], rsum[4][2];

    #pragma unroll
    for (int mi = 0; mi < 4; mi++)
        #pragma unroll
        for (int h = 0; h < 2; h++) {
            float v = -3.4e38f;
            #pragma unroll
            for (int ni = 0; ni < 4; ni++)
                v = fmaxf(v, fmaxf(acc[mi][ni][2 * h], acc[mi][ni][2 * h + 1]));
            v = fmaxf(v, __shfl_xor_sync(0xFFFFFFFFu, v, 1));
            v = fmaxf(v, __shfl_xor_sync(0xFFFFFFFFu, v, 2));
            pmax[mi][h] = v;
        }
    __syncthreads();   // mainloop smem reads done before reuse as 'red'
    if (tg == 0)
        #pragma unroll
        for (int mi = 0; mi < 4; mi++)
            #pragma unroll
            for (int h = 0; h < 2; h++)
                red[(wm * 64 + mi * 16 + g + 8 * h) * 8 + wn] = pmax[mi][h];
    __syncthreads();
    #pragma unroll
    for (int mi = 0; mi < 4; mi++)
        #pragma unroll
        for (int h = 0; h < 2; h++) {
            const int wr = wm * 64 + mi * 16 + g + 8 * h;
            float v = red[wr * 8 + 0];
            #pragma unroll
            for (int j = 1; j < 8; j++) v = fmaxf(v, red[wr * 8 + j]);
            rmax[mi][h] = v;
        }
    __syncthreads();

    #pragma unroll
    for (int mi = 0; mi < 4; mi++)
        #pragma unroll
        for (int h = 0; h < 2; h++) {
            float s = 0.f;
            #pragma unroll
            for (int ni = 0; ni < 4; ni++) {
                float e0 = __expf(acc[mi][ni][2 * h]     - rmax[mi][h]);
                float e1 = __expf(acc[mi][ni][2 * h + 1] - rmax[mi][h]);
                acc[mi][ni][2 * h]     = e0;
                acc[mi][ni][2 * h + 1] = e1;
                s += e0 + e1;
            }
            s += __shfl_xor_sync(0xFFFFFFFFu, s, 1);
            s += __shfl_xor_sync(0xFFFFFFFFu, s, 2);
            psum[mi][h] = s;
        }
    if (tg == 0)
        #pragma unroll
        for (int mi = 0; mi < 4; mi++)
            #pragma unroll
            for (int h = 0; h < 2; h++)
                red[(wm * 64 + mi * 16 + g + 8 * h) * 8 + wn] = psum[mi][h];
    __syncthreads();
    #pragma unroll
    for (int mi = 0; mi < 4; mi++)
        #pragma unroll
        for (int h = 0; h < 2; h++) {
            const int wr = wm * 64 + mi * 16 + g + 8 * h;
            float s = red[wr * 8 + 0];
            #pragma unroll
            for (int j = 1; j < 8; j++) s += red[wr * 8 + j];
            rsum[mi][h] = 1.0f / s;
        }

    #pragma unroll
    for (int mi = 0; mi < 4; mi++)
        #pragma unroll
        for (int ni = 0; ni < 4; ni++) {
            const int col = wn * 32 + ni * 8 + 2 * tg;
            const int r0 = m0 + wm * 64 + mi * 16 + g;
            *(float2*)(outF + (size_t)r0 * 256 + col) =
                make_float2(acc[mi][ni][0] * rsum[mi][0],
                            acc[mi][ni][1] * rsum[mi][0]);
            *(float2*)(outF + (size_t)(r0 + 8) * 256 + col) =
                make_float2(acc[mi][ni][2] * rsum[mi][1],
                            acc[mi][ni][3] * rsum[mi][1]);
        }
}

// ---------------- launch ----------------
extern "C" void kernel_launch(void* const* d_in, const int* in_sizes, int n_in,
                              void* d_out, int out_size)
{
    (void)in_sizes; (void)n_in; (void)out_size;
    const float* data = (const float*)d_in[0];
    const float* W1   = (const float*)d_in[1];
    const float* b1   = (const float*)d_in[2];
    const float* a1   = (const float*)d_in[3];
    const float* W2   = (const float*)d_in[4];
    const float* b2   = (const float*)d_in[5];
    const float* a2   = (const float*)d_in[6];
    const float* W3   = (const float*)d_in[7];
    const float* b3   = (const float*)d_in[8];
    const float* a3   = (const float*)d_in[9];
    float* out = (float*)d_out;

    void* p;
    cudaGetSymbolAddress(&p, g_dH);  uint32_t* dH  = (uint32_t*)p;
    cudaGetSymbolAddress(&p, g_dL);  uint32_t* dL  = (uint32_t*)p;
    cudaGetSymbolAddress(&p, g_h1H); uint32_t* h1H = (uint32_t*)p;
    cudaGetSymbolAddress(&p, g_h1L); uint32_t* h1L = (uint32_t*)p;
    cudaGetSymbolAddress(&p, g_h2H); uint32_t* h2H = (uint32_t*)p;
    cudaGetSymbolAddress(&p, g_h2L); uint32_t* h2L = (uint32_t*)p;
    cudaGetSymbolAddress(&p, g_wH);  uint32_t* wH  = (uint32_t*)p;
    cudaGetSymbolAddress(&p, g_wL);  uint32_t* wL  = (uint32_t*)p;

    cudaFuncSetAttribute(gemm_s, cudaFuncAttributeMaxDynamicSharedMemorySize,
                         2 * S_STAGE);
    cudaFuncSetAttribute(gemm_l3, cudaFuncAttributeMaxDynamicSharedMemorySize,
                         2 * L_STAGE);

    prep_w_all<<<1024, 256>>>(W1, W2, W3, wH, wL);
    prep_a<<<(BATCH * 64 + 255) / 256, 256>>>(data, dH, dL, BATCH * 64);

    // layers 1-2: 64x128 tiles, 2 CTAs/SM; grid.x fastest -> column CTAs of the
    // same A-row tile are adjacent (co-resident -> A hits L2)
    gemm_s<<<dim3(4, BATCH / S_MT), NTHREADS_S, 2 * S_STAGE>>>(
        dH, dL, wH, wL, b1, a1, h1H, h1L, 256, 512);
    gemm_s<<<dim3(4, BATCH / S_MT), NTHREADS_S, 2 * S_STAGE>>>(
        h1H, h1L, wH + 65536, wL + 65536, b2, a2, h2H, h2L, 512, 512);
    // layer 3 + fused softmax: 128x256 tile
    gemm_l3<<<dim3(1, BATCH / L_MT), NTHREADS_L, 2 * L_STAGE>>>(
        h2H, h2L, wH + 196608, wL + 196608, b3, a3, out, 512);
}

// round 16
// speedup vs baseline: 1.3651x; 1.0397x over previous
#include <cuda_runtime.h>
#include <cuda_fp16.h>
#include <cstdint>

// ---------------------------------------------------------------------------
// Network_1760936591970 (sm_103): fp16 2-split (Dekker) x 3-MMA emulated-fp32
// GEMM on mma.sync.m16n8k16.f16.
// R16: ldmatrix.m8n8.x4 fragment loads (4x fewer shared-load instructions,
// bit-identical fragment values). Layers 1-2: 256-thread CTAs (64x128 tile,
// 2 CTAs/SM). Layer 3: 512-thread 128x256 kernel with fused row softmax.
// 128B XOR-swizzled rows, BKT=64, 2-stage single-barrier cp.async pipeline.
// 256 -> 512 -> 512 -> 256 MLP, B=65536, fp32 I/O.
// ---------------------------------------------------------------------------

#define BATCH 65536
#define NTHREADS_S 256
#define NTHREADS_L 512

// small kernel (layers 1-2): 64x128 tile
#define S_MT 64
#define S_NT 128
#define S_AH 0
#define S_AL 8192
#define S_BH 16384
#define S_BL 32768
#define S_STAGE 49152          // 48KB; x2 stages = 96KB

// large kernel (layer 3): 128x256 tile
#define L_MT 128
#define L_NT 256
#define L_AH 0
#define L_AL 16384
#define L_BH 32768
#define L_BL 65536
#define L_STAGE 98304          // 96KB; x2 stages = 192KB

// pre-split scratch (uint32 = packed half2 covering k,k+1)
__device__ uint32_t g_dH[BATCH * 128];     // data   [B][256/2]
__device__ uint32_t g_dL[BATCH * 128];
__device__ uint32_t g_h1H[BATCH * 256];    // h1     [B][512/2]
__device__ uint32_t g_h1L[BATCH * 256];
__device__ uint32_t g_h2H[BATCH * 256];    // h2     [B][512/2]
__device__ uint32_t g_h2L[BATCH * 256];
// weights transposed [N][K/2]: L1 @0, L2 @65536, L3 @196608
__device__ uint32_t g_wH[262144];
__device__ uint32_t g_wL[262144];

// ---------------- helpers ----------------
__device__ __forceinline__ void split_h(float x, uint16_t& h, uint16_t& l) {
    __half hh = __float2half_rn(x);
    __half ll = __float2half_rn(x - __half2float(hh));
    h = __half_as_ushort(hh);
    l = __half_as_ushort(ll);
}
__device__ __forceinline__ uint32_t pack2(uint16_t a, uint16_t b) {
    return (uint32_t)a | ((uint32_t)b << 16);
}
__device__ __forceinline__ uint32_t smem_u32(const void* p) {
    uint32_t a;
    asm("{ .reg .u64 t; cvta.to.shared.u64 t, %1; cvt.u32.u64 %0, t; }" : "=r"(a) : "l"(p));
    return a;
}
__device__ __forceinline__ void mma16(float* c, const uint32_t* a, uint32_t b0, uint32_t b1) {
    asm volatile(
        "mma.sync.aligned.m16n8k16.row.col.f32.f16.f16.f32 "
        "{%0,%1,%2,%3},{%4,%5,%6,%7},{%8,%9},{%0,%1,%2,%3};"
        : "+f"(c[0]), "+f"(c[1]), "+f"(c[2]), "+f"(c[3])
        : "r"(a[0]), "r"(a[1]), "r"(a[2]), "r"(a[3]), "r"(b0), "r"(b1));
}
__device__ __forceinline__ void ldsm4(uint32_t* r, uint32_t addr) {
    asm volatile("ldmatrix.sync.aligned.m8n8.x4.shared.b16 {%0,%1,%2,%3}, [%4];"
        : "=r"(r[0]), "=r"(r[1]), "=r"(r[2]), "=r"(r[3]) : "r"(addr));
}
__device__ __forceinline__ void cpa16(uint32_t dst, const void* src) {
    asm volatile("cp.async.cg.shared.global [%0], [%1], 16;" :: "r"(dst), "l"(src));
}
__device__ __forceinline__ float fast_tanh(float x) {
    float xc = fminf(fmaxf(x, -10.f), 10.f);
    float t = __expf(2.f * xc);
    return __fdividef(t - 1.f, t + 1.f);
}
__device__ __forceinline__ float act_f(float x, const float* a) {
    return a[1] * fast_tanh(x) * sinf(a[2] * x + a[3]) + a[4] * x + a[5];
}
#define ROWOFF(row, kbyte) ((row) * 128 + ((kbyte) ^ (((row) & 7) << 4)))

// ---------------- prep kernels ----------------
__global__ void prep_w_all(const float* __restrict__ W1, const float* __restrict__ W2,
                           const float* __restrict__ W3,
                           uint32_t* __restrict__ th, uint32_t* __restrict__ tl)
{
    int i = blockIdx.x * 256 + threadIdx.x;        // 0 .. 262143
    const float* W; int K, N, base;
    if (i < 65536)       { W = W1; K = 256; N = 512; base = 0; }
    else if (i < 196608) { W = W2; K = 512; N = 512; base = 65536; }
    else                 { W = W3; K = 512; N = 256; base = 196608; }
    const int j = i - base, Kp = K >> 1;
    const int n = j / Kp, p = j - n * Kp;
    uint16_t h0, l0, h1, l1;
    split_h(W[(size_t)(2 * p) * N + n], h0, l0);
    split_h(W[(size_t)(2 * p + 1) * N + n], h1, l1);
    th[i] = pack2(h0, h1);
    tl[i] = pack2(l0, l1);
}
__global__ void prep_a(const float* __restrict__ A, uint32_t* __restrict__ th,
                       uint32_t* __restrict__ tl, int n4)
{
    int i = blockIdx.x * 256 + threadIdx.x;
    if (i >= n4) return;
    float4 v = *(const float4*)(A + (size_t)i * 4);
    uint16_t h0, l0, h1, l1, h2, l2, h3, l3;
    split_h(v.x, h0, l0); split_h(v.y, h1, l1);
    split_h(v.z, h2, l2); split_h(v.w, h3, l3);
    th[2 * i]     = pack2(h0, h1);  tl[2 * i]     = pack2(l0, l1);
    th[2 * i + 1] = pack2(h2, h3);  tl[2 * i + 1] = pack2(l2, l3);
}

// lane-constant ldmatrix address pieces:
// A (x4 over 16 rows x k16): arow = (l&7) + ((l>>3)&1)*8, aksel = (l>>4)*16
// B (x4 over 16 n-rows x k16): brow = (l&7) + ((l>>4)&1)*8, bksel = ((l>>3)&1)*16
// full addr = base + (tile_row + {a,b}row)*128 + ((kk*32 + {a,b}ksel) ^ ((l&7)<<4))

// ---------------- small GEMM: 64x128 tile, 2 CTAs/SM, layers 1-2 ----------------
__global__ void __launch_bounds__(NTHREADS_S, 2)
gemm_s(const uint32_t* __restrict__ AH, const uint32_t* __restrict__ AL,
       const uint32_t* __restrict__ BH, const uint32_t* __restrict__ BL,
       const float* __restrict__ bias, const float* __restrict__ actp,
       uint32_t* __restrict__ outH, uint32_t* __restrict__ outL, int K, int Nn)
{
    extern __shared__ char smem[];
    __shared__ float psm[S_NT * 6];

    const int tid  = threadIdx.x;
    const int lane = tid & 31;
    const int warp = tid >> 5;
    const int wm   = warp & 1;    // 0..1 -> 32-row half
    const int wn   = warp >> 1;   // 0..3 -> 32-col block
    const int g    = lane >> 2;
    const int tg   = lane & 3;
    const int m0   = blockIdx.y * S_MT;
    const int n0   = blockIdx.x * S_NT;
    const int Kp   = K >> 1;
    const uint32_t sb = smem_u32(smem);

    // ldmatrix lane constants
    const uint32_t lsw   = (uint32_t)(lane & 7) << 4;
    const uint32_t arow  = (lane & 7) + ((lane >> 3) & 1) * 8;
    const uint32_t aksel = (lane >> 4) * 16;
    const uint32_t brow  = (lane & 7) + ((lane >> 4) & 1) * 8;
    const uint32_t bksel = ((lane >> 3) & 1) * 16;
    const uint32_t aRowBase = (wm * 32 + arow) * 128;     // + mi*2048
    const uint32_t bRowBase = (wn * 32 + brow) * 128;     // + np*2048

    for (int c = tid; c < S_NT; c += NTHREADS_S) {
        psm[c * 6 + 0] = bias[n0 + c];
        #pragma unroll
        for (int j = 0; j < 5; j++) psm[c * 6 + 1 + j] = actp[(n0 + c) * 5 + j];
    }

    float acc[2][4][4];
    #pragma unroll
    for (int i = 0; i < 2; i++)
        #pragma unroll
        for (int j = 0; j < 4; j++)
            #pragma unroll
            for (int c = 0; c < 4; c++) acc[i][j][c] = 0.f;

    const int kIters = K / 64;            // BKT=64: 4 (K=256) or 8 (K=512)
    const int cr = tid >> 3, cq = tid & 7;

    auto issue = [&](int it) {
        const uint32_t stb = sb + (it & 1) * S_STAGE;
        const int p0 = it * 32;
        #pragma unroll
        for (int i = 0; i < 2; i++) {      // A hi+lo: 64 rows x 8 chunks
            const int m = cr + i * 32;
            const uint32_t off = ROWOFF(m, cq * 16);
            const size_t src = (size_t)(m0 + m) * Kp + p0 + cq * 4;
            cpa16(stb + S_AH + off, AH + src);
            cpa16(stb + S_AL + off, AL + src);
        }
        #pragma unroll
        for (int i = 0; i < 4; i++) {      // B hi+lo: 128 rows x 8 chunks
            const int n = cr + i * 32;
            const uint32_t off = ROWOFF(n, cq * 16);
            const size_t src = (size_t)(n0 + n) * Kp + p0 + cq * 4;
            cpa16(stb + S_BH + off, BH + src);
            cpa16(stb + S_BL + off, BL + src);
        }
        asm volatile("cp.async.commit_group;" ::: "memory");
    };

    issue(0);

    for (int it = 0; it < kIters; it++) {
        asm volatile("cp.async.wait_group 0;" ::: "memory");
        __syncthreads();
        if (it + 1 < kIters) issue(it + 1);

        const uint32_t stb = sb + (it & 1) * S_STAGE;
        #pragma unroll
        for (int kk = 0; kk < 4; kk++) {   // 4 k16-slices per stage
            const uint32_t kA = ((uint32_t)(kk * 32) + aksel) ^ lsw;
            const uint32_t kB = ((uint32_t)(kk * 32) + bksel) ^ lsw;
            uint32_t ah[2][4], al[2][4];
            #pragma unroll
            for (int mi = 0; mi < 2; mi++) {
                const uint32_t ra = aRowBase + mi * 2048;
                ldsm4(ah[mi], stb + S_AH + ra + kA);
                ldsm4(al[mi], stb + S_AL + ra + kA);
            }
            #pragma unroll
            for (int np = 0; np < 2; np++) {
                uint32_t bh4[4], bl4[4];
                const uint32_t rb = bRowBase + np * 2048;
                ldsm4(bh4, stb + S_BH + rb + kB);
                ldsm4(bl4, stb + S_BL + rb + kB);
                #pragma unroll
                for (int p = 0; p < 2; p++)
                    #pragma unroll
                    for (int mi = 0; mi < 2; mi++)
                        mma16(acc[mi][np * 2 + p], ah[mi], bh4[p * 2], bh4[p * 2 + 1]);
                #pragma unroll
                for (int p = 0; p < 2; p++)
                    #pragma unroll
                    for (int mi = 0; mi < 2; mi++)
                        mma16(acc[mi][np * 2 + p], al[mi], bh4[p * 2], bh4[p * 2 + 1]);
                #pragma unroll
                for (int p = 0; p < 2; p++)
                    #pragma unroll
                    for (int mi = 0; mi < 2; mi++)
                        mma16(acc[mi][np * 2 + p], ah[mi], bl4[p * 2], bl4[p * 2 + 1]);
            }
        }
    }

    // epilogue: bias + activation + split-store
    const int Np = Nn >> 1;
    #pragma unroll
    for (int mi = 0; mi < 2; mi++)
        #pragma unroll
        for (int ni = 0; ni < 4; ni++) {
            const int cw = wn * 32 + ni * 8 + 2 * tg;
            const float* p0 = &psm[cw * 6];
            const float* p1 = &psm[(cw + 1) * 6];
            const int cp = (n0 + cw) >> 1;
            const int r0 = m0 + wm * 32 + mi * 16 + g;
            float v0 = act_f(acc[mi][ni][0] + p0[0], p0);
            float v1 = act_f(acc[mi][ni][1] + p1[0], p1);
            float v2 = act_f(acc[mi][ni][2] + p0[0], p0);
            float v3 = act_f(acc[mi][ni][3] + p1[0], p1);
            uint16_t h0, l0, h1, l1;
            split_h(v0, h0, l0); split_h(v1, h1, l1);
            outH[(size_t)r0 * Np + cp] = pack2(h0, h1);
            outL[(size_t)r0 * Np + cp] = pack2(l0, l1);
            split_h(v2, h0, l0); split_h(v3, h1, l1);
            outH[(size_t)(r0 + 8) * Np + cp] = pack2(h0, h1);
            outL[(size_t)(r0 + 8) * Np + cp] = pack2(l0, l1);
        }
}

// ---------------- large GEMM: 128x256 tile, layer 3 + fused softmax ----------------
__global__ void __launch_bounds__(NTHREADS_L, 1)
gemm_l3(const uint32_t* __restrict__ AH, const uint32_t* __restrict__ AL,
        const uint32_t* __restrict__ BH, const uint32_t* __restrict__ BL,
        const float* __restrict__ bias, const float* __restrict__ actp,
        float* __restrict__ outF, int K)
{
    extern __shared__ char smem[];
    __shared__ float psm[L_NT * 6];

    const int tid  = threadIdx.x;
    const int lane = tid & 31;
    const int warp = tid >> 5;
    const int wm   = warp & 1;
    const int wn   = warp >> 1;
    const int g    = lane >> 2;
    const int tg   = lane & 3;
    const int m0   = blockIdx.y * L_MT;
    const int Kp   = K >> 1;
    const uint32_t sb = smem_u32(smem);

    const uint32_t lsw   = (uint32_t)(lane & 7) << 4;
    const uint32_t arow  = (lane & 7) + ((lane >> 3) & 1) * 8;
    const uint32_t aksel = (lane >> 4) * 16;
    const uint32_t brow  = (lane & 7) + ((lane >> 4) & 1) * 8;
    const uint32_t bksel = ((lane >> 3) & 1) * 16;
    const uint32_t aRowBase = (wm * 64 + arow) * 128;
    const uint32_t bRowBase = (wn * 32 + brow) * 128;

    for (int c = tid; c < L_NT; c += NTHREADS_L) {
        psm[c * 6 + 0] = bias[c];
        #pragma unroll
        for (int j = 0; j < 5; j++) psm[c * 6 + 1 + j] = actp[c * 5 + j];
    }

    float acc[4][4][4];
    #pragma unroll
    for (int i = 0; i < 4; i++)
        #pragma unroll
        for (int j = 0; j < 4; j++)
            #pragma unroll
            for (int c = 0; c < 4; c++) acc[i][j][c] = 0.f;

    const int kIters = K / 64;
    const int cr = tid >> 3, cq = tid & 7;

    auto issue = [&](int it) {
        const uint32_t stb = sb + (it & 1) * L_STAGE;
        const int p0 = it * 32;
        #pragma unroll
        for (int i = 0; i < 2; i++) {          // A hi+lo: 128 rows
            const int m = cr + i * 64;
            const uint32_t off = ROWOFF(m, cq * 16);
            const size_t src = (size_t)(m0 + m) * Kp + p0 + cq * 4;
            cpa16(stb + L_AH + off, AH + src);
            cpa16(stb + L_AL + off, AL + src);
        }
        #pragma unroll
        for (int i = 0; i < 4; i++) {          // B hi+lo: 256 rows
            const int n = cr + i * 64;
            const uint32_t off = ROWOFF(n, cq * 16);
            const size_t src = (size_t)n * Kp + p0 + cq * 4;
            cpa16(stb + L_BH + off, BH + src);
            cpa16(stb + L_BL + off, BL + src);
        }
        asm volatile("cp.async.commit_group;" ::: "memory");
    };

    issue(0);

    for (int it = 0; it < kIters; it++) {
        asm volatile("cp.async.wait_group 0;" ::: "memory");
        __syncthreads();
        if (it + 1 < kIters) issue(it + 1);

        const uint32_t stb = sb + (it & 1) * L_STAGE;
        #pragma unroll
        for (int kk = 0; kk < 4; kk++) {
            const uint32_t kA = ((uint32_t)(kk * 32) + aksel) ^ lsw;
            const uint32_t kB = ((uint32_t)(kk * 32) + bksel) ^ lsw;
            uint32_t ah[4][4], al[4][4];
            #pragma unroll
            for (int mi = 0; mi < 4; mi++) {
                const uint32_t ra = aRowBase + mi * 2048;
                ldsm4(ah[mi], stb + L_AH + ra + kA);
                ldsm4(al[mi], stb + L_AL + ra + kA);
            }
            #pragma unroll
            for (int np = 0; np < 2; np++) {
                uint32_t bh4[4], bl4[4];
                const uint32_t rb = bRowBase + np * 2048;
                ldsm4(bh4, stb + L_BH + rb + kB);
                ldsm4(bl4, stb + L_BL + rb + kB);
                #pragma unroll
                for (int p = 0; p < 2; p++)
                    #pragma unroll
                    for (int mi = 0; mi < 4; mi++)
                        mma16(acc[mi][np * 2 + p], ah[mi], bh4[p * 2], bh4[p * 2 + 1]);
                #pragma unroll
                for (int p = 0; p < 2; p++)
                    #pragma unroll
                    for (int mi = 0; mi < 4; mi++)
                        mma16(acc[mi][np * 2 + p], al[mi], bh4[p * 2], bh4[p * 2 + 1]);
                #pragma unroll
                for (int p = 0; p < 2; p++)
                    #pragma unroll
                    for (int mi = 0; mi < 4; mi++)
                        mma16(acc[mi][np * 2 + p], ah[mi], bl4[p * 2], bl4[p * 2 + 1]);
            }
        }
    }

    // epilogue: bias + activation
    #pragma unroll
    for (int mi = 0; mi < 4; mi++)
        #pragma unroll
        for (int ni = 0; ni < 4; ni++) {
            const int cw = wn * 32 + ni * 8 + 2 * tg;
            const float* p0 = &psm[cw * 6];
            const float* p1 = &psm[(cw + 1) * 6];
            acc[mi][ni][0] = act_f(acc[mi][ni][0] + p0[0], p0);
            acc[mi][ni][1] = act_f(acc[mi][ni][1] + p1[0], p1);
            acc[mi][ni][2] = act_f(acc[mi][ni][2] + p0[0], p0);
            acc[mi][ni][3] = act_f(acc[mi][ni][3] + p1[0], p1);
        }

    // fused softmax over full row (256 cols in this CTA); 8 wn partials
    float* red = (float*)smem;   // [128 rows][8]
    float pmax[4][2], rmax[4][2], psum[4][2], rsum[4][2];

    #pragma unroll
    for (int mi = 0; mi < 4; mi++)
        #pragma unroll
        for (int h = 0; h < 2; h++) {
            float v = -3.4e38f;
            #pragma unroll
            for (int ni = 0; ni < 4; ni++)
                v = fmaxf(v, fmaxf(acc[mi][ni][2 * h], acc[mi][ni][2 * h + 1]));
            v = fmaxf(v, __shfl_xor_sync(0xFFFFFFFFu, v, 1));
            v = fmaxf(v, __shfl_xor_sync(0xFFFFFFFFu, v, 2));
            pmax[mi][h] = v;
        }
    __syncthreads();   // mainloop smem reads done before reuse as 'red'
    if (tg == 0)
        #pragma unroll
        for (int mi = 0; mi < 4; mi++)
            #pragma unroll
            for (int h = 0; h < 2; h++)
                red[(wm * 64 + mi * 16 + g + 8 * h) * 8 + wn] = pmax[mi][h];
    __syncthreads();
    #pragma unroll
    for (int mi = 0; mi < 4; mi++)
        #pragma unroll
        for (int h = 0; h < 2; h++) {
            const int wr = wm * 64 + mi * 16 + g + 8 * h;
            float v = red[wr * 8 + 0];
            #pragma unroll
            for (int j = 1; j < 8; j++) v = fmaxf(v, red[wr * 8 + j]);
            rmax[mi][h] = v;
        }
    __syncthreads();

    #pragma unroll
    for (int mi = 0; mi < 4; mi++)
        #pragma unroll
        for (int h = 0; h < 2; h++) {
            float s = 0.f;
            #pragma unroll
            for (int ni = 0; ni < 4; ni++) {
                float e0 = __expf(acc[mi][ni][2 * h]     - rmax[mi][h]);
                float e1 = __expf(acc[mi][ni][2 * h + 1] - rmax[mi][h]);
                acc[mi][ni][2 * h]     = e0;
                acc[mi][ni][2 * h + 1] = e1;
                s += e0 + e1;
            }
            s += __shfl_xor_sync(0xFFFFFFFFu, s, 1);
            s += __shfl_xor_sync(0xFFFFFFFFu, s, 2);
            psum[mi][h] = s;
        }
    if (tg == 0)
        #pragma unroll
        for (int mi = 0; mi < 4; mi++)
            #pragma unroll
            for (int h = 0; h < 2; h++)
                red[(wm * 64 + mi * 16 + g + 8 * h) * 8 + wn] = psum[mi][h];
    __syncthreads();
    #pragma unroll
    for (int mi = 0; mi < 4; mi++)
        #pragma unroll
        for (int h = 0; h < 2; h++) {
            const int wr = wm * 64 + mi * 16 + g + 8 * h;
            float s = red[wr * 8 + 0];
            #pragma unroll
            for (int j = 1; j < 8; j++) s += red[wr * 8 + j];
            rsum[mi][h] = 1.0f / s;
        }

    #pragma unroll
    for (int mi = 0; mi < 4; mi++)
        #pragma unroll
        for (int ni = 0; ni < 4; ni++) {
            const int col = wn * 32 + ni * 8 + 2 * tg;
            const int r0 = m0 + wm * 64 + mi * 16 + g;
            *(float2*)(outF + (size_t)r0 * 256 + col) =
                make_float2(acc[mi][ni][0] * rsum[mi][0],
                            acc[mi][ni][1] * rsum[mi][0]);
            *(float2*)(outF + (size_t)(r0 + 8) * 256 + col) =
                make_float2(acc[mi][ni][2] * rsum[mi][1],
                            acc[mi][ni][3] * rsum[mi][1]);
        }
}

// ---------------- launch ----------------
extern "C" void kernel_launch(void* const* d_in, const int* in_sizes, int n_in,
                              void* d_out, int out_size)
{
    (void)in_sizes; (void)n_in; (void)out_size;
    const float* data = (const float*)d_in[0];
    const float* W1   = (const float*)d_in[1];
    const float* b1   = (const float*)d_in[2];
    const float* a1   = (const float*)d_in[3];
    const float* W2   = (const float*)d_in[4];
    const float* b2   = (const float*)d_in[5];
    const float* a2   = (const float*)d_in[6];
    const float* W3   = (const float*)d_in[7];
    const float* b3   = (const float*)d_in[8];
    const float* a3   = (const float*)d_in[9];
    float* out = (float*)d_out;

    void* p;
    cudaGetSymbolAddress(&p, g_dH);  uint32_t* dH  = (uint32_t*)p;
    cudaGetSymbolAddress(&p, g_dL);  uint32_t* dL  = (uint32_t*)p;
    cudaGetSymbolAddress(&p, g_h1H); uint32_t* h1H = (uint32_t*)p;
    cudaGetSymbolAddress(&p, g_h1L); uint32_t* h1L = (uint32_t*)p;
    cudaGetSymbolAddress(&p, g_h2H); uint32_t* h2H = (uint32_t*)p;
    cudaGetSymbolAddress(&p, g_h2L); uint32_t* h2L = (uint32_t*)p;
    cudaGetSymbolAddress(&p, g_wH);  uint32_t* wH  = (uint32_t*)p;
    cudaGetSymbolAddress(&p, g_wL);  uint32_t* wL  = (uint32_t*)p;

    cudaFuncSetAttribute(gemm_s, cudaFuncAttributeMaxDynamicSharedMemorySize,
                         2 * S_STAGE);
    cudaFuncSetAttribute(gemm_l3, cudaFuncAttributeMaxDynamicSharedMemorySize,
                         2 * L_STAGE);

    prep_w_all<<<1024, 256>>>(W1, W2, W3, wH, wL);
    prep_a<<<(BATCH * 64 + 255) / 256, 256>>>(data, dH, dL, BATCH * 64);

    // layers 1-2: 64x128 tiles, 2 CTAs/SM; grid.x fastest -> column CTAs of the
    // same A-row tile are adjacent (co-resident -> A hits L2)
    gemm_s<<<dim3(4, BATCH / S_MT), NTHREADS_S, 2 * S_STAGE>>>(
        dH, dL, wH, wL, b1, a1, h1H, h1L, 256, 512);
    gemm_s<<<dim3(4, BATCH / S_MT), NTHREADS_S, 2 * S_STAGE>>>(
        h1H, h1L, wH + 65536, wL + 65536, b2, a2, h2H, h2L, 512, 512);
    // layer 3 + fused softmax: 128x256 tile
    gemm_l3<<<dim3(1, BATCH / L_MT), NTHREADS_L, 2 * L_STAGE>>>(
        h2H, h2L, wH + 196608, wL + 196608, b3, a3, out, 512);
}